// round 3
// baseline (speedup 1.0000x reference)
#include <cuda_runtime.h>
#include <math.h>

// Problem constants (fixed by the dataset)
#define NMAX   50000
#define EMAX   800000
#define IN_C   128
#define HID_C  128
#define OUT_C  64
#define LPA_ITER 5

// ---------------- device scratch (no allocations allowed) ----------------
__device__ int   g_is64;                  // 1 if edge_index is int64, 0 if int32
__device__ float g_deg [NMAX];
__device__ float g_dinv[NMAX];
__device__ int   g_cnt [NMAX];
__device__ int   g_rowptr[NMAX + 1];
__device__ int   g_cur [NMAX];
__device__ int2  g_cv  [EMAX];            // packed (col, val bits) sorted by row
__device__ float g_xw  [NMAX * HID_C];    // x @ w1
__device__ float g_h   [NMAX * HID_C];    // relu(spmm(xw)+b1)
__device__ float g_hw  [NMAX * OUT_C];    // h @ w2
__device__ float g_lab [2][NMAX * OUT_C]; // LPA ping-pong

// ---------------- edge-index dtype detection (on-device, capturable) ------
__global__ void k_detect(const void* __restrict__ ei, int E, int N) {
    if (threadIdx.x == 0 && blockIdx.x == 0) {
        const long long* q = (const long long*)ei;
        int ok64 = 1;
        int lim = (2 * E < 64) ? 2 * E : 64;   // reads only first 512 bytes: safe either way
        for (int i = 0; i < lim; i++) {
            long long v = q[i];
            if (v < 0 || v >= (long long)N) { ok64 = 0; break; }
        }
        g_is64 = ok64;
    }
}

__device__ __forceinline__ int load_idx(const void* p, size_t i, int is64) {
    if (is64) return (int)((const long long*)p)[i];
    return ((const int*)p)[i];
}

// ---------------- preprocessing kernels ----------------
__global__ void k_zero(int n) {
    int i = blockIdx.x * blockDim.x + threadIdx.x;
    if (i < n) { g_deg[i] = 0.f; g_cnt[i] = 0; }
}

__global__ void k_deg(const void* __restrict__ ei,
                      const float* __restrict__ ea, int E, int N) {
    int e = blockIdx.x * blockDim.x + threadIdx.x;
    if (e < E) {
        int is64 = g_is64;
        int r = load_idx(ei, e, is64);
        if ((unsigned)r < (unsigned)N) {
            atomicAdd(&g_deg[r], ea[e]);
            atomicAdd(&g_cnt[r], 1);
        }
    }
}

__global__ void k_dinv(int n) {
    int i = blockIdx.x * blockDim.x + threadIdx.x;
    if (i < n) {
        float d = g_deg[i];
        g_dinv[i] = (d != 0.f) ? (1.f / d) : 0.f;
    }
}

// one-block exclusive scan of g_cnt -> g_rowptr / g_cur
__global__ void k_scan(int n) {
    __shared__ int sums[1024];
    int tid = threadIdx.x;
    int chunk = (n + 1023) / 1024;
    int start = tid * chunk;
    int end   = min(start + chunk, n);
    int s = 0;
    for (int i = start; i < end; i++) s += g_cnt[i];
    sums[tid] = s;
    __syncthreads();
    for (int off = 1; off < 1024; off <<= 1) {
        int v = (tid >= off) ? sums[tid - off] : 0;
        __syncthreads();
        sums[tid] += v;
        __syncthreads();
    }
    int run = sums[tid] - s;      // exclusive prefix
    for (int i = start; i < end; i++) {
        g_rowptr[i] = run;
        g_cur[i]    = run;
        run += g_cnt[i];
    }
    if (tid == 1023) g_rowptr[n] = sums[1023];
}

__global__ void k_scatter(const void* __restrict__ ei,
                          const float* __restrict__ ea, int E, int N) {
    int e = blockIdx.x * blockDim.x + threadIdx.x;
    if (e < E) {
        int is64 = g_is64;
        int r = load_idx(ei, e, is64);
        int c = load_idx(ei, (size_t)E + e, is64);
        if ((unsigned)r < (unsigned)N && (unsigned)c < (unsigned)N) {
            int pos = atomicAdd(&g_cur[r], 1);
            float v = ea[e] * g_dinv[r];
            g_cv[pos] = make_int2(c, __float_as_int(v));
        }
    }
}

// ---------------- dense GEMM: out[n,Ctot] = A[n,128] @ W[128,Ctot] ----------------
// block: 256 threads, computes 32 rows x 64 cols (blockIdx.y selects col half)
__global__ __launch_bounds__(256) void k_gemm(const float* __restrict__ A,
                                              const float* __restrict__ W,
                                              float* __restrict__ out,
                                              int n, int Ctot) {
    __shared__ float ws[128][64];   // 32 KB
    __shared__ float xs[32][128];   // 16 KB
    int colbase = blockIdx.y * 64;
    int rowbase = blockIdx.x * 32;
    int tid = threadIdx.x;

    for (int i = tid; i < 128 * 64; i += 256) {
        int k = i >> 6, c = i & 63;
        ws[k][c] = W[k * Ctot + colbase + c];
    }
    int rows = min(32, n - rowbase);
    for (int i = tid; i < rows * 128; i += 256) {
        int r = i >> 7, k = i & 127;
        xs[r][k] = A[(size_t)(rowbase + r) * 128 + k];
    }
    __syncthreads();

    int warp = tid >> 5, lane = tid & 31;
    int r0 = warp * 4;
    float2 acc0 = {0.f, 0.f}, acc1 = {0.f, 0.f}, acc2 = {0.f, 0.f}, acc3 = {0.f, 0.f};
#pragma unroll 8
    for (int k = 0; k < 128; k++) {
        float2 wv = *(const float2*)&ws[k][lane * 2];
        float x0 = xs[r0 + 0][k];
        float x1 = xs[r0 + 1][k];
        float x2 = xs[r0 + 2][k];
        float x3 = xs[r0 + 3][k];
        acc0.x += x0 * wv.x; acc0.y += x0 * wv.y;
        acc1.x += x1 * wv.x; acc1.y += x1 * wv.y;
        acc2.x += x2 * wv.x; acc2.y += x2 * wv.y;
        acc3.x += x3 * wv.x; acc3.y += x3 * wv.y;
    }
    float2 accs[4] = {acc0, acc1, acc2, acc3};
#pragma unroll
    for (int r = 0; r < 4; r++) {
        int row = rowbase + r0 + r;
        if (row < n)
            *(float2*)&out[(size_t)row * Ctot + colbase + lane * 2] = accs[r];
    }
}

// ---------------- SPMM: dst[r,:] = sum_{j in row r} val_j * src[col_j,:] ----------------
// EPI: 0 = none, 1 = relu(+bias), 2 = sigmoid(+bias), 3 = sigmoid (no bias)
template <int F, int EPI>
__global__ __launch_bounds__(256) void k_spmm(const float* __restrict__ src,
                                              const float* __restrict__ bias,
                                              float* __restrict__ dst, int n) {
    int w = (blockIdx.x * blockDim.x + threadIdx.x) >> 5;
    int lane = threadIdx.x & 31;
    if (w >= n) return;
    int beg = g_rowptr[w];
    int end = g_rowptr[w + 1];

    if (F == 128) {
        float4 acc = {0.f, 0.f, 0.f, 0.f};
        int j = beg;
        for (; j + 1 < end; j += 2) {
            int2 cv0 = g_cv[j];
            int2 cv1 = g_cv[j + 1];
            float v0 = __int_as_float(cv0.y);
            float v1 = __int_as_float(cv1.y);
            float4 s0 = *(const float4*)&src[(size_t)cv0.x * 128 + lane * 4];
            float4 s1 = *(const float4*)&src[(size_t)cv1.x * 128 + lane * 4];
            acc.x += v0 * s0.x; acc.y += v0 * s0.y; acc.z += v0 * s0.z; acc.w += v0 * s0.w;
            acc.x += v1 * s1.x; acc.y += v1 * s1.y; acc.z += v1 * s1.z; acc.w += v1 * s1.w;
        }
        if (j < end) {
            int2 cv = g_cv[j];
            float v = __int_as_float(cv.y);
            float4 s = *(const float4*)&src[(size_t)cv.x * 128 + lane * 4];
            acc.x += v * s.x; acc.y += v * s.y; acc.z += v * s.z; acc.w += v * s.w;
        }
        if (EPI == 1) {
            float4 b = *(const float4*)&bias[lane * 4];
            acc.x = fmaxf(acc.x + b.x, 0.f);
            acc.y = fmaxf(acc.y + b.y, 0.f);
            acc.z = fmaxf(acc.z + b.z, 0.f);
            acc.w = fmaxf(acc.w + b.w, 0.f);
        }
        *(float4*)&dst[(size_t)w * 128 + lane * 4] = acc;
    } else {  // F == 64
        float2 acc = {0.f, 0.f};
        int j = beg;
        for (; j + 1 < end; j += 2) {
            int2 cv0 = g_cv[j];
            int2 cv1 = g_cv[j + 1];
            float v0 = __int_as_float(cv0.y);
            float v1 = __int_as_float(cv1.y);
            float2 s0 = *(const float2*)&src[(size_t)cv0.x * 64 + lane * 2];
            float2 s1 = *(const float2*)&src[(size_t)cv1.x * 64 + lane * 2];
            acc.x += v0 * s0.x; acc.y += v0 * s0.y;
            acc.x += v1 * s1.x; acc.y += v1 * s1.y;
        }
        if (j < end) {
            int2 cv = g_cv[j];
            float v = __int_as_float(cv.y);
            float2 s = *(const float2*)&src[(size_t)cv.x * 64 + lane * 2];
            acc.x += v * s.x; acc.y += v * s.y;
        }
        if (EPI == 2) {
            float2 b = *(const float2*)&bias[lane * 2];
            acc.x = 1.f / (1.f + __expf(-(acc.x + b.x)));
            acc.y = 1.f / (1.f + __expf(-(acc.y + b.y)));
        } else if (EPI == 3) {
            acc.x = 1.f / (1.f + __expf(-acc.x));
            acc.y = 1.f / (1.f + __expf(-acc.y));
        }
        *(float2*)&dst[(size_t)w * 64 + lane * 2] = acc;
    }
}

// ---------------- host launch ----------------
static void* sym_addr(const void* sym) {
    void* p = nullptr;
    cudaGetSymbolAddress(&p, sym);
    return p;
}

extern "C" void kernel_launch(void* const* d_in, const int* in_sizes, int n_in,
                              void* d_out, int out_size) {
    const float* x    = (const float*)d_in[0];
    const float* soft = (const float*)d_in[1];
    const float* ea   = (const float*)d_in[2];
    const float* w1   = (const float*)d_in[3];
    const float* b1   = (const float*)d_in[4];
    const float* w2   = (const float*)d_in[5];
    const float* b2   = (const float*)d_in[6];
    const void*  ei   = (const void*)d_in[7];   // int32 or int64, detected on device

    int N = in_sizes[0] / IN_C;
    int E = in_sizes[2];

    float* out     = (float*)d_out;
    float* out_x   = out;
    float* out_lab = out + (size_t)N * OUT_C;

    float* xw  = (float*)sym_addr(g_xw);
    float* h   = (float*)sym_addr(g_h);
    float* hw  = (float*)sym_addr(g_hw);
    float* la  = (float*)sym_addr(g_lab);   // g_lab[0]
    float* lb  = la + (size_t)NMAX * OUT_C; // g_lab[1]

    int tb = 256;

    // --- build row-normalized CSR ---
    k_detect<<<1, 32>>>(ei, E, N);
    k_zero<<<(N + tb - 1) / tb, tb>>>(N);
    k_deg<<<(E + tb - 1) / tb, tb>>>(ei, ea, E, N);
    k_dinv<<<(N + tb - 1) / tb, tb>>>(N);
    k_scan<<<1, 1024>>>(N);
    k_scatter<<<(E + tb - 1) / tb, tb>>>(ei, ea, E, N);

    // --- GCN layer 1: h = relu(spmm(x@w1) + b1) ---
    dim3 g1((N + 31) / 32, 2);
    k_gemm<<<g1, 256>>>(x, w1, xw, N, HID_C);
    int spmm_blocks = (N + 7) / 8;  // warp per row, 8 warps/block
    k_spmm<128, 1><<<spmm_blocks, 256>>>(xw, b1, h, N);

    // --- GCN layer 2: out_x = sigmoid(spmm(h@w2) + b2) ---
    dim3 g2((N + 31) / 32, 1);
    k_gemm<<<g2, 256>>>(h, w2, hw, N, OUT_C);
    k_spmm<64, 2><<<spmm_blocks, 256>>>(hw, b2, out_x, N);

    // --- LPA: 5x spmm, sigmoid on the last ---
    k_spmm<64, 0><<<spmm_blocks, 256>>>(soft, nullptr, la, N);   // iter 1
    k_spmm<64, 0><<<spmm_blocks, 256>>>(la, nullptr, lb, N);     // iter 2
    k_spmm<64, 0><<<spmm_blocks, 256>>>(lb, nullptr, la, N);     // iter 3
    k_spmm<64, 0><<<spmm_blocks, 256>>>(la, nullptr, lb, N);     // iter 4
    k_spmm<64, 3><<<spmm_blocks, 256>>>(lb, nullptr, out_lab, N);// iter 5 + sigmoid
}